// round 3
// baseline (speedup 1.0000x reference)
#include <cuda_runtime.h>
#include <cuda_bf16.h>
#include <math.h>

#define N_TOK 4096
#define EMBED 1024
#define NHEAD 16
#define HDIM 64
#define FFN 4096
#define QKV3 3072

// ---------------- scratch (device globals; no cudaMalloc allowed) ----------
__device__ alignas(16) float g_qkv[N_TOK * QKV3];      // 50 MB
__device__ alignas(16) float g_attn[N_TOK * EMBED];    // 16.8 MB
__device__ alignas(16) float g_res1[N_TOK * EMBED];
__device__ alignas(16) float g_h[N_TOK * EMBED];
__device__ alignas(16) float g_ffn[N_TOK * FFN];       // 67 MB

// ---------------- SGEMM: C = A(MxK) @ W(KxN) + bias [+resid | gelu] --------
// EPI: 0 = bias only, 1 = bias + resid, 2 = bias + gelu
// All global accesses scalar (input pointers' alignment untrusted).
// Vector accesses only on alignas(16) smem at 16B-multiple offsets.
template <int EPI>
__global__ void __launch_bounds__(256)
gemm_kernel(const float* __restrict__ A, const float* __restrict__ W,
            const float* __restrict__ bias, const float* __restrict__ resid,
            float* __restrict__ C, int M, int N, int K) {
    __shared__ alignas(16) float As[16][132];
    __shared__ alignas(16) float Bs[16][132];

    const int tid = threadIdx.x;
    const int m0 = blockIdx.y * 128;
    const int n0 = blockIdx.x * 128;
    const int ty = tid >> 4;          // 0..15
    const int tx = tid & 15;          // 0..15

    float acc[8][8];
#pragma unroll
    for (int i = 0; i < 8; i++)
#pragma unroll
        for (int j = 0; j < 8; j++) acc[i][j] = 0.f;

    for (int k0 = 0; k0 < K; k0 += 16) {
#pragma unroll
        for (int u = 0; u < 2; u++) {
            int f = tid + u * 256;
            // A tile: 128 rows x 16 cols, stored transposed (scalar loads)
            int ar = f >> 2;
            int ak = (f & 3) * 4;
            const float* ap = &A[(size_t)(m0 + ar) * K + k0 + ak];
            As[ak + 0][ar] = ap[0];
            As[ak + 1][ar] = ap[1];
            As[ak + 2][ar] = ap[2];
            As[ak + 3][ar] = ap[3];
            // B tile: 16 rows x 128 cols (scalar loads)
            int br = f >> 5;
            int bn = (f & 31) * 4;
            const float* wp = &W[(size_t)(k0 + br) * N + n0 + bn];
            Bs[br][bn + 0] = wp[0];
            Bs[br][bn + 1] = wp[1];
            Bs[br][bn + 2] = wp[2];
            Bs[br][bn + 3] = wp[3];
        }
        __syncthreads();
#pragma unroll
        for (int kk = 0; kk < 16; kk++) {
            // offsets: kk*132 floats = 528B (16B mult), ty*8 floats = 32B (16B mult)
            float4 a0 = *(const float4*)&As[kk][ty * 8];
            float4 a1 = *(const float4*)&As[kk][ty * 8 + 4];
            float4 b0 = *(const float4*)&Bs[kk][tx * 8];
            float4 b1 = *(const float4*)&Bs[kk][tx * 8 + 4];
            float a[8] = {a0.x, a0.y, a0.z, a0.w, a1.x, a1.y, a1.z, a1.w};
            float b[8] = {b0.x, b0.y, b0.z, b0.w, b1.x, b1.y, b1.z, b1.w};
#pragma unroll
            for (int i = 0; i < 8; i++)
#pragma unroll
                for (int j = 0; j < 8; j++) acc[i][j] = fmaf(a[i], b[j], acc[i][j]);
        }
        __syncthreads();
    }

#pragma unroll
    for (int i = 0; i < 8; i++) {
        int r = m0 + ty * 8 + i;
#pragma unroll
        for (int j = 0; j < 8; j++) {
            int c = n0 + tx * 8 + j;
            float v = acc[i][j] + bias[c];
            if (EPI == 1) v += resid[(size_t)r * N + c];
            if (EPI == 2) {
                float x = v;
                float t = tanhf(0.7978845608028654f * (x + 0.044715f * x * x * x));
                v = 0.5f * x * (1.f + t);
            }
            C[(size_t)r * N + c] = v;
        }
    }
}

// ---------------- RoPE (in-place on q,k of g_qkv) --------------------------
__global__ void rope_kernel(float* __restrict__ qkv, const float* __restrict__ coords,
                            const float* __restrict__ inv_freq) {
    int n = blockIdx.x;
    __shared__ alignas(16) float cs[32];
    __shared__ alignas(16) float sn[32];
    int t = threadIdx.x;  // 256
    if (t < 32) {
        int d = t >> 3, f = t & 7;
        float ang = coords[n * 4 + d] * inv_freq[d * 8 + f];
        cs[t] = cosf(ang);
        sn[t] = sinf(ang);
    }
    __syncthreads();
#pragma unroll
    for (int w = t; w < 1024; w += 256) {
        int qk = w >> 9;               // 0 = q, 1 = k
        int h = (w >> 5) & 15;
        int p = w & 31;
        float* base = qkv + (size_t)n * QKV3 + qk * EMBED + h * HDIM;
        float x1 = base[p], x2 = base[p + 32];
        base[p]      = x1 * cs[p] - x2 * sn[p];
        base[p + 32] = x2 * cs[p] + x1 * sn[p];
    }
}

// ---------------- Flash-style segment attention ----------------------------
// grid: (N_TOK/64, NHEAD), block: 64 threads (1 query each)
__global__ void __launch_bounds__(64)
attn_kernel(const float* __restrict__ qkv, const int* __restrict__ cu,
            float* __restrict__ out) {
    const int h = blockIdx.y;
    const int tid = threadIdx.x;
    const int qi = blockIdx.x * 64 + tid;

    int s = 0;
#pragma unroll
    for (int i = 1; i <= 7; i++)
        if (cu[i] <= qi) s = i;
    const int kstart = cu[s];
    const int kend = cu[s + 1];

    __shared__ int skb, ske;
    if (tid == 0) { skb = kstart; ske = kend; }
    __syncthreads();
    atomicMin(&skb, kstart);
    atomicMax(&ske, kend);
    __syncthreads();
    const int kb0 = skb & ~63;
    const int keM = ske;

    __shared__ alignas(16) float Ks[64 * 64];
    __shared__ alignas(16) float Vs[64 * 64];

    float q[64], o[64];
    {
        const float* qp = qkv + (size_t)qi * QKV3 + h * HDIM;
#pragma unroll
        for (int d = 0; d < 64; d++) {
            q[d] = qp[d] * 0.125f;  // 1/sqrt(64)
            o[d] = 0.f;
        }
    }
    float m = -1e30f, l = 0.f;

    for (int kt = kb0; kt < keM; kt += 64) {
        {
            int tok = kt + tid;
            const float* kp = qkv + (size_t)tok * QKV3 + EMBED + h * HDIM;
            const float* vp = qkv + (size_t)tok * QKV3 + 2 * EMBED + h * HDIM;
            float4* kd = (float4*)&Ks[tid * 64];
            float4* vd = (float4*)&Vs[tid * 64];
#pragma unroll
            for (int d4 = 0; d4 < 16; d4++) {
                kd[d4] = ((const float4*)kp)[d4];
                vd[d4] = ((const float4*)vp)[d4];
            }
        }
        __syncthreads();

#pragma unroll 1
        for (int jc = 0; jc < 64; jc += 16) {
            float sc[16];
#pragma unroll
            for (int jj = 0; jj < 16; jj++) {
                const float4* kr = (const float4*)&Ks[(jc + jj) * 64];
                float a0 = 0.f, a1 = 0.f, a2 = 0.f, a3 = 0.f;
#pragma unroll
                for (int d4 = 0; d4 < 16; d4++) {
                    float4 kv = kr[d4];
                    a0 = fmaf(q[d4 * 4 + 0], kv.x, a0);
                    a1 = fmaf(q[d4 * 4 + 1], kv.y, a1);
                    a2 = fmaf(q[d4 * 4 + 2], kv.z, a2);
                    a3 = fmaf(q[d4 * 4 + 3], kv.w, a3);
                }
                int kg = kt + jc + jj;
                bool valid = (kg >= kstart) && (kg < kend);
                sc[jj] = valid ? (a0 + a1) + (a2 + a3) : -1e30f;
            }
            float cm = -1e30f;
#pragma unroll
            for (int jj = 0; jj < 16; jj++) cm = fmaxf(cm, sc[jj]);
            float mn = fmaxf(m, cm);
            float scale = expf(m - mn);
            l *= scale;
#pragma unroll
            for (int d = 0; d < 64; d++) o[d] *= scale;
            float p[16];
            float ps = 0.f;
#pragma unroll
            for (int jj = 0; jj < 16; jj++) {
                int kg = kt + jc + jj;
                bool valid = (kg >= kstart) && (kg < kend);
                p[jj] = valid ? expf(sc[jj] - mn) : 0.f;
                ps += p[jj];
            }
            l += ps;
            m = mn;
#pragma unroll
            for (int d4 = 0; d4 < 16; d4++) {
                float o0 = o[d4 * 4 + 0], o1 = o[d4 * 4 + 1];
                float o2 = o[d4 * 4 + 2], o3 = o[d4 * 4 + 3];
#pragma unroll
                for (int jj = 0; jj < 16; jj++) {
                    float4 vv = *(const float4*)&Vs[(jc + jj) * 64 + d4 * 4];
                    o0 = fmaf(p[jj], vv.x, o0);
                    o1 = fmaf(p[jj], vv.y, o1);
                    o2 = fmaf(p[jj], vv.z, o2);
                    o3 = fmaf(p[jj], vv.w, o3);
                }
                o[d4 * 4 + 0] = o0; o[d4 * 4 + 1] = o1;
                o[d4 * 4 + 2] = o2; o[d4 * 4 + 3] = o3;
            }
        }
        __syncthreads();
    }

    float inv_l = 1.f / l;
    float* op = out + (size_t)qi * EMBED + h * HDIM;
#pragma unroll
    for (int d = 0; d < 64; d++) op[d] = o[d] * inv_l;
}

// ---------------- LayerNorm: one block per row (1024 elems) ----------------
__device__ __forceinline__ float blockReduceSum(float v) {
    __shared__ alignas(16) float red[8];
    int lane = threadIdx.x & 31, wid = threadIdx.x >> 5;
#pragma unroll
    for (int off = 16; off; off >>= 1) v += __shfl_xor_sync(0xffffffffu, v, off);
    __syncthreads();
    if (lane == 0) red[wid] = v;
    __syncthreads();
    v = (threadIdx.x < 8) ? red[threadIdx.x] : 0.f;
    if (wid == 0) {
#pragma unroll
        for (int off = 4; off; off >>= 1) v += __shfl_xor_sync(0xffu, v, off);
        if (lane == 0) red[0] = v;
    }
    __syncthreads();
    return red[0];
}

// x is aligned scratch (float4 OK). g/b harness inputs (scalar). y scalar.
__global__ void __launch_bounds__(256)
layernorm_kernel(const float* __restrict__ x, const float* __restrict__ g,
                 const float* __restrict__ b, float* __restrict__ y) {
    int row = blockIdx.x;
    int t = threadIdx.x;
    const float4* xr = (const float4*)(x + (size_t)row * EMBED);
    float4 v = xr[t];
    float s = (v.x + v.y) + (v.z + v.w);
    float mean = blockReduceSum(s) * (1.f / 1024.f);
    float dx = v.x - mean, dy = v.y - mean, dz = v.z - mean, dw = v.w - mean;
    float sq = dx * dx + dy * dy + dz * dz + dw * dw;
    float var = blockReduceSum(sq) * (1.f / 1024.f);
    float rstd = rsqrtf(var + 1e-5f);
    int c = t * 4;
    float g0 = g[c], g1 = g[c + 1], g2 = g[c + 2], g3 = g[c + 3];
    float b0 = b[c], b1 = b[c + 1], b2 = b[c + 2], b3 = b[c + 3];
    float* yr = y + (size_t)row * EMBED + c;
    yr[0] = dx * rstd * g0 + b0;
    yr[1] = dy * rstd * g1 + b1;
    yr[2] = dz * rstd * g2 + b2;
    yr[3] = dw * rstd * g3 + b3;
}

// ---------------- launch ---------------------------------------------------
extern "C" void kernel_launch(void* const* d_in, const int* in_sizes, int n_in,
                              void* d_out, int out_size) {
    const float* coords   = (const float*)d_in[0];
    const float* feats    = (const float*)d_in[1];
    const int*   cu       = (const int*)d_in[2];
    const float* Wqkv     = (const float*)d_in[3];
    const float* bqkv     = (const float*)d_in[4];
    const float* Wo       = (const float*)d_in[5];
    const float* bo       = (const float*)d_in[6];
    const float* inv_freq = (const float*)d_in[7];
    const float* ln1_g    = (const float*)d_in[8];
    const float* ln1_b    = (const float*)d_in[9];
    const float* W1       = (const float*)d_in[10];
    const float* b1       = (const float*)d_in[11];
    const float* W2       = (const float*)d_in[12];
    const float* b2       = (const float*)d_in[13];
    const float* ln2_g    = (const float*)d_in[14];
    const float* ln2_b    = (const float*)d_in[15];
    float* out = (float*)d_out;

    float *qkv, *attn, *res1, *h, *ffn;
    cudaGetSymbolAddress((void**)&qkv, g_qkv);
    cudaGetSymbolAddress((void**)&attn, g_attn);
    cudaGetSymbolAddress((void**)&res1, g_res1);
    cudaGetSymbolAddress((void**)&h, g_h);
    cudaGetSymbolAddress((void**)&ffn, g_ffn);

    // 1. QKV projection
    gemm_kernel<0><<<dim3(QKV3 / 128, N_TOK / 128), 256>>>(
        feats, Wqkv, bqkv, nullptr, qkv, N_TOK, QKV3, EMBED);
    // 2. RoPE on q,k
    rope_kernel<<<N_TOK, 256>>>(qkv, coords, inv_freq);
    // 3. Segment attention
    attn_kernel<<<dim3(N_TOK / 64, NHEAD), 64>>>(qkv, cu, attn);
    // 4. Wo projection + residual(feats)
    gemm_kernel<1><<<dim3(EMBED / 128, N_TOK / 128), 256>>>(
        attn, Wo, bo, feats, res1, N_TOK, EMBED, EMBED);
    // 5. LN1 -> h
    layernorm_kernel<<<N_TOK, 256>>>(res1, ln1_g, ln1_b, h);
    // 6. FFN up + gelu
    gemm_kernel<2><<<dim3(FFN / 128, N_TOK / 128), 256>>>(
        h, W1, b1, nullptr, ffn, N_TOK, FFN, EMBED);
    // 7. FFN down + residual(h)
    gemm_kernel<1><<<dim3(EMBED / 128, N_TOK / 128), 256>>>(
        ffn, W2, b2, h, res1, N_TOK, EMBED, FFN);
    // 8. LN2 -> out
    layernorm_kernel<<<N_TOK, 256>>>(res1, ln2_g, ln2_b, out);
}

// round 4
// speedup vs baseline: 1.4270x; 1.4270x over previous
#include <cuda_runtime.h>
#include <cuda_bf16.h>
#include <math.h>
#include <stdint.h>

#define N_TOK 4096
#define EMBED 1024
#define NHEAD 16
#define HDIM 64
#define FFN 4096
#define QKV3 3072

// ---------------- scratch (device globals; no cudaMalloc allowed) ----------
__device__ alignas(16) float g_qkv[N_TOK * QKV3];      // 50 MB
__device__ alignas(16) float g_attn[N_TOK * EMBED];    // 16.8 MB
__device__ alignas(16) float g_res1[N_TOK * EMBED];
__device__ alignas(16) float g_h[N_TOK * EMBED];
__device__ alignas(16) float g_ffn[N_TOK * FFN];       // 67 MB

// ---------------- TF32 tensor-core GEMM ------------------------------------
// C = A(MxK) @ W(KxN) + bias [+resid | gelu]
// 128x128 block tile, BK=32, 256 threads = 8 warps, warp tile 64x32.
// mma.sync.aligned.m16n8k8.row.col.f32.tf32.tf32.f32

__device__ __forceinline__ uint32_t f2tf32(float x) {
    uint32_t u;
    asm("cvt.rna.tf32.f32 %0, %1;" : "=r"(u) : "f"(x));
    return u;
}

__device__ __forceinline__ void mma_tf32(float* c, const uint32_t* a, const uint32_t* b) {
    asm volatile(
        "mma.sync.aligned.m16n8k8.row.col.f32.tf32.tf32.f32 "
        "{%0,%1,%2,%3}, {%4,%5,%6,%7}, {%8,%9}, {%0,%1,%2,%3};"
        : "+f"(c[0]), "+f"(c[1]), "+f"(c[2]), "+f"(c[3])
        : "r"(a[0]), "r"(a[1]), "r"(a[2]), "r"(a[3]), "r"(b[0]), "r"(b[1]));
}

// EPI: 0 = bias, 1 = bias + resid, 2 = bias + gelu
template <int EPI>
__global__ void __launch_bounds__(256)
gemm_tc_kernel(const float* __restrict__ A, const float* __restrict__ W,
               const float* __restrict__ bias, const float* __restrict__ resid,
               float* __restrict__ C, int M, int N, int K) {
    // pads chosen for conflict-free fragment reads:
    // As bank = (4*row + col) % 32 ; Bs bank = (8*row + col) % 32
    __shared__ alignas(16) uint32_t As[128][36];
    __shared__ alignas(16) uint32_t Bs[32][136];

    const int tid = threadIdx.x;
    const int wid = tid >> 5;
    const int lane = tid & 31;
    const int g = lane >> 2;    // group id 0..7
    const int t = lane & 3;     // thread-in-group 0..3
    const int m0 = blockIdx.y * 128;
    const int n0 = blockIdx.x * 128;
    const int wm = (wid & 1) * 64;     // warp m offset
    const int wn = (wid >> 1) * 32;    // warp n offset

    float acc[4][4][4];
#pragma unroll
    for (int i = 0; i < 4; i++)
#pragma unroll
        for (int j = 0; j < 4; j++)
#pragma unroll
            for (int r = 0; r < 4; r++) acc[i][j][r] = 0.f;

    for (int k0 = 0; k0 < K; k0 += 32) {
        // load A tile 128x32 and B tile 32x128 (scalar global, tf32 convert)
#pragma unroll
        for (int i = 0; i < 16; i++) {
            int idx = tid + i * 256;
            int ar = idx >> 5, ac = idx & 31;
            As[ar][ac] = f2tf32(A[(size_t)(m0 + ar) * K + k0 + ac]);
            int bk = idx >> 7, bn = idx & 127;
            Bs[bk][bn] = f2tf32(W[(size_t)(k0 + bk) * N + n0 + bn]);
        }
        __syncthreads();

#pragma unroll
        for (int ks = 0; ks < 4; ks++) {
            uint32_t a[4][4];
#pragma unroll
            for (int mt = 0; mt < 4; mt++) {
                int r = wm + mt * 16 + g;
                int c = ks * 8 + t;
                a[mt][0] = As[r][c];
                a[mt][1] = As[r + 8][c];
                a[mt][2] = As[r][c + 4];
                a[mt][3] = As[r + 8][c + 4];
            }
            uint32_t b[4][2];
#pragma unroll
            for (int nt = 0; nt < 4; nt++) {
                int c = wn + nt * 8 + g;
                b[nt][0] = Bs[ks * 8 + t][c];
                b[nt][1] = Bs[ks * 8 + t + 4][c];
            }
#pragma unroll
            for (int mt = 0; mt < 4; mt++)
#pragma unroll
                for (int nt = 0; nt < 4; nt++)
                    mma_tf32(acc[mt][nt], a[mt], b[nt]);
        }
        __syncthreads();
    }

    // epilogue: c0=(g, 2t), c1=(g, 2t+1), c2=(g+8, 2t), c3=(g+8, 2t+1)
#pragma unroll
    for (int mt = 0; mt < 4; mt++) {
#pragma unroll
        for (int nt = 0; nt < 4; nt++) {
            int r0 = m0 + wm + mt * 16 + g;
            int c0 = n0 + wn + nt * 8 + 2 * t;
#pragma unroll
            for (int half = 0; half < 2; half++) {
                int r = r0 + half * 8;
#pragma unroll
                for (int e = 0; e < 2; e++) {
                    int c = c0 + e;
                    float v = acc[mt][nt][half * 2 + e] + bias[c];
                    if (EPI == 1) v += resid[(size_t)r * N + c];
                    if (EPI == 2) {
                        float x = v;
                        float th = tanhf(0.7978845608028654f *
                                         (x + 0.044715f * x * x * x));
                        v = 0.5f * x * (1.f + th);
                    }
                    C[(size_t)r * N + c] = v;
                }
            }
        }
    }
}

// ---------------- RoPE (in-place on q,k of g_qkv) --------------------------
__global__ void rope_kernel(float* __restrict__ qkv, const float* __restrict__ coords,
                            const float* __restrict__ inv_freq) {
    int n = blockIdx.x;
    __shared__ alignas(16) float cs[32];
    __shared__ alignas(16) float sn[32];
    int t = threadIdx.x;  // 256
    if (t < 32) {
        int d = t >> 3, f = t & 7;
        float ang = coords[n * 4 + d] * inv_freq[d * 8 + f];
        cs[t] = cosf(ang);
        sn[t] = sinf(ang);
    }
    __syncthreads();
#pragma unroll
    for (int w = t; w < 1024; w += 256) {
        int qk = w >> 9;
        int h = (w >> 5) & 15;
        int p = w & 31;
        float* base = qkv + (size_t)n * QKV3 + qk * EMBED + h * HDIM;
        float x1 = base[p], x2 = base[p + 32];
        base[p]      = x1 * cs[p] - x2 * sn[p];
        base[p + 32] = x2 * cs[p] + x1 * sn[p];
    }
}

// ---------------- Flash-style segment attention ----------------------------
__global__ void __launch_bounds__(64)
attn_kernel(const float* __restrict__ qkv, const int* __restrict__ cu,
            float* __restrict__ out) {
    const int h = blockIdx.y;
    const int tid = threadIdx.x;
    const int qi = blockIdx.x * 64 + tid;

    int s = 0;
#pragma unroll
    for (int i = 1; i <= 7; i++)
        if (cu[i] <= qi) s = i;
    const int kstart = cu[s];
    const int kend = cu[s + 1];

    __shared__ int skb, ske;
    if (tid == 0) { skb = kstart; ske = kend; }
    __syncthreads();
    atomicMin(&skb, kstart);
    atomicMax(&ske, kend);
    __syncthreads();
    const int kb0 = skb & ~63;
    const int keM = ske;

    __shared__ alignas(16) float Ks[64 * 64];
    __shared__ alignas(16) float Vs[64 * 64];

    float q[64], o[64];
    {
        const float* qp = qkv + (size_t)qi * QKV3 + h * HDIM;
#pragma unroll
        for (int d = 0; d < 64; d++) {
            q[d] = qp[d] * 0.125f;
            o[d] = 0.f;
        }
    }
    float m = -1e30f, l = 0.f;

    for (int kt = kb0; kt < keM; kt += 64) {
        {
            int tok = kt + tid;
            const float* kp = qkv + (size_t)tok * QKV3 + EMBED + h * HDIM;
            const float* vp = qkv + (size_t)tok * QKV3 + 2 * EMBED + h * HDIM;
            float4* kd = (float4*)&Ks[tid * 64];
            float4* vd = (float4*)&Vs[tid * 64];
#pragma unroll
            for (int d4 = 0; d4 < 16; d4++) {
                kd[d4] = ((const float4*)kp)[d4];
                vd[d4] = ((const float4*)vp)[d4];
            }
        }
        __syncthreads();

#pragma unroll 1
        for (int jc = 0; jc < 64; jc += 16) {
            float sc[16];
#pragma unroll
            for (int jj = 0; jj < 16; jj++) {
                const float4* kr = (const float4*)&Ks[(jc + jj) * 64];
                float a0 = 0.f, a1 = 0.f, a2 = 0.f, a3 = 0.f;
#pragma unroll
                for (int d4 = 0; d4 < 16; d4++) {
                    float4 kv = kr[d4];
                    a0 = fmaf(q[d4 * 4 + 0], kv.x, a0);
                    a1 = fmaf(q[d4 * 4 + 1], kv.y, a1);
                    a2 = fmaf(q[d4 * 4 + 2], kv.z, a2);
                    a3 = fmaf(q[d4 * 4 + 3], kv.w, a3);
                }
                int kg = kt + jc + jj;
                bool valid = (kg >= kstart) && (kg < kend);
                sc[jj] = valid ? (a0 + a1) + (a2 + a3) : -1e30f;
            }
            float cm = -1e30f;
#pragma unroll
            for (int jj = 0; jj < 16; jj++) cm = fmaxf(cm, sc[jj]);
            float mn = fmaxf(m, cm);
            float scale = expf(m - mn);
            l *= scale;
#pragma unroll
            for (int d = 0; d < 64; d++) o[d] *= scale;
            float p[16];
            float ps = 0.f;
#pragma unroll
            for (int jj = 0; jj < 16; jj++) {
                int kg = kt + jc + jj;
                bool valid = (kg >= kstart) && (kg < kend);
                p[jj] = valid ? expf(sc[jj] - mn) : 0.f;
                ps += p[jj];
            }
            l += ps;
            m = mn;
#pragma unroll
            for (int d4 = 0; d4 < 16; d4++) {
                float o0 = o[d4 * 4 + 0], o1 = o[d4 * 4 + 1];
                float o2 = o[d4 * 4 + 2], o3 = o[d4 * 4 + 3];
#pragma unroll
                for (int jj = 0; jj < 16; jj++) {
                    float4 vv = *(const float4*)&Vs[(jc + jj) * 64 + d4 * 4];
                    o0 = fmaf(p[jj], vv.x, o0);
                    o1 = fmaf(p[jj], vv.y, o1);
                    o2 = fmaf(p[jj], vv.z, o2);
                    o3 = fmaf(p[jj], vv.w, o3);
                }
                o[d4 * 4 + 0] = o0; o[d4 * 4 + 1] = o1;
                o[d4 * 4 + 2] = o2; o[d4 * 4 + 3] = o3;
            }
        }
        __syncthreads();
    }

    float inv_l = 1.f / l;
    float* op = out + (size_t)qi * EMBED + h * HDIM;
#pragma unroll
    for (int d = 0; d < 64; d++) op[d] = o[d] * inv_l;
}

// ---------------- LayerNorm ------------------------------------------------
__device__ __forceinline__ float blockReduceSum(float v) {
    __shared__ alignas(16) float red[8];
    int lane = threadIdx.x & 31, wid = threadIdx.x >> 5;
#pragma unroll
    for (int off = 16; off; off >>= 1) v += __shfl_xor_sync(0xffffffffu, v, off);
    __syncthreads();
    if (lane == 0) red[wid] = v;
    __syncthreads();
    v = (threadIdx.x < 8) ? red[threadIdx.x] : 0.f;
    if (wid == 0) {
#pragma unroll
        for (int off = 4; off; off >>= 1) v += __shfl_xor_sync(0xffu, v, off);
        if (lane == 0) red[0] = v;
    }
    __syncthreads();
    return red[0];
}

__global__ void __launch_bounds__(256)
layernorm_kernel(const float* __restrict__ x, const float* __restrict__ g,
                 const float* __restrict__ b, float* __restrict__ y) {
    int row = blockIdx.x;
    int t = threadIdx.x;
    const float4* xr = (const float4*)(x + (size_t)row * EMBED);
    float4 v = xr[t];
    float s = (v.x + v.y) + (v.z + v.w);
    float mean = blockReduceSum(s) * (1.f / 1024.f);
    float dx = v.x - mean, dy = v.y - mean, dz = v.z - mean, dw = v.w - mean;
    float sq = dx * dx + dy * dy + dz * dz + dw * dw;
    float var = blockReduceSum(sq) * (1.f / 1024.f);
    float rstd = rsqrtf(var + 1e-5f);
    int c = t * 4;
    float g0 = g[c], g1 = g[c + 1], g2 = g[c + 2], g3 = g[c + 3];
    float b0 = b[c], b1 = b[c + 1], b2 = b[c + 2], b3 = b[c + 3];
    float* yr = y + (size_t)row * EMBED + c;
    yr[0] = dx * rstd * g0 + b0;
    yr[1] = dy * rstd * g1 + b1;
    yr[2] = dz * rstd * g2 + b2;
    yr[3] = dw * rstd * g3 + b3;
}

// ---------------- launch ---------------------------------------------------
extern "C" void kernel_launch(void* const* d_in, const int* in_sizes, int n_in,
                              void* d_out, int out_size) {
    const float* coords   = (const float*)d_in[0];
    const float* feats    = (const float*)d_in[1];
    const int*   cu       = (const int*)d_in[2];
    const float* Wqkv     = (const float*)d_in[3];
    const float* bqkv     = (const float*)d_in[4];
    const float* Wo       = (const float*)d_in[5];
    const float* bo       = (const float*)d_in[6];
    const float* inv_freq = (const float*)d_in[7];
    const float* ln1_g    = (const float*)d_in[8];
    const float* ln1_b    = (const float*)d_in[9];
    const float* W1       = (const float*)d_in[10];
    const float* b1       = (const float*)d_in[11];
    const float* W2       = (const float*)d_in[12];
    const float* b2       = (const float*)d_in[13];
    const float* ln2_g    = (const float*)d_in[14];
    const float* ln2_b    = (const float*)d_in[15];
    float* out = (float*)d_out;

    float *qkv, *attn, *res1, *h, *ffn;
    cudaGetSymbolAddress((void**)&qkv, g_qkv);
    cudaGetSymbolAddress((void**)&attn, g_attn);
    cudaGetSymbolAddress((void**)&res1, g_res1);
    cudaGetSymbolAddress((void**)&h, g_h);
    cudaGetSymbolAddress((void**)&ffn, g_ffn);

    // 1. QKV projection
    gemm_tc_kernel<0><<<dim3(QKV3 / 128, N_TOK / 128), 256>>>(
        feats, Wqkv, bqkv, nullptr, qkv, N_TOK, QKV3, EMBED);
    // 2. RoPE on q,k
    rope_kernel<<<N_TOK, 256>>>(qkv, coords, inv_freq);
    // 3. Segment attention
    attn_kernel<<<dim3(N_TOK / 64, NHEAD), 64>>>(qkv, cu, attn);
    // 4. Wo projection + residual(feats)
    gemm_tc_kernel<1><<<dim3(EMBED / 128, N_TOK / 128), 256>>>(
        attn, Wo, bo, feats, res1, N_TOK, EMBED, EMBED);
    // 5. LN1 -> h
    layernorm_kernel<<<N_TOK, 256>>>(res1, ln1_g, ln1_b, h);
    // 6. FFN up + gelu
    gemm_tc_kernel<2><<<dim3(FFN / 128, N_TOK / 128), 256>>>(
        h, W1, b1, nullptr, ffn, N_TOK, FFN, EMBED);
    // 7. FFN down + residual(h)
    gemm_tc_kernel<1><<<dim3(EMBED / 128, N_TOK / 128), 256>>>(
        ffn, W2, b2, h, res1, N_TOK, EMBED, FFN);
    // 8. LN2 -> out
    layernorm_kernel<<<N_TOK, 256>>>(res1, ln2_g, ln2_b, out);
}

// round 5
// speedup vs baseline: 1.9380x; 1.3581x over previous
#include <cuda_runtime.h>
#include <cuda_bf16.h>
#include <math.h>
#include <stdint.h>

#define N_TOK 4096
#define EMBED 1024
#define NHEAD 16
#define HDIM 64
#define FFN 4096
#define QKV3 3072

// ---------------- scratch (device globals; no cudaMalloc allowed) ----------
__device__ alignas(16) float g_qkv[N_TOK * QKV3];
__device__ alignas(16) float g_attn[N_TOK * EMBED];
__device__ alignas(16) float g_res1[N_TOK * EMBED];
__device__ alignas(16) float g_h[N_TOK * EMBED];
__device__ alignas(16) float g_ffn[N_TOK * FFN];
// aligned (+tf32-rounded) copies of unaligned harness inputs
__device__ alignas(16) float g_feats_a[N_TOK * EMBED];
__device__ alignas(16) float g_wqkv[EMBED * QKV3];
__device__ alignas(16) float g_wo[EMBED * EMBED];
__device__ alignas(16) float g_w1[EMBED * FFN];
__device__ alignas(16) float g_w2[FFN * EMBED];

__device__ __forceinline__ uint32_t f2tf32(float x) {
    uint32_t u;
    asm("cvt.rna.tf32.f32 %0, %1;" : "=r"(u) : "f"(x));
    return u;
}

// copy + round-to-tf32 (so GEMM loads need no conversion; mma truncation exact)
__global__ void copy_tf32_kernel(const float* __restrict__ src,
                                 float* __restrict__ dst, int n) {
    int i = blockIdx.x * blockDim.x + threadIdx.x;
    if (i < n) dst[i] = __uint_as_float(f2tf32(src[i]));
}

// ---------------- TF32 tensor-core GEMM with cp.async 3-stage pipeline -----
#define NSTAGE 3
#define ASTRIDE 36     // floats per A row (pad 4) -> 144B, 16B mult
#define BSTRIDE 136    // floats per B row (pad 8) -> 544B, 16B mult
#define A_TILE (128 * ASTRIDE)
#define B_TILE (32 * BSTRIDE)
#define STAGE_FLOATS (A_TILE + B_TILE)
#define GEMM_SMEM_BYTES (NSTAGE * STAGE_FLOATS * 4)

__device__ __forceinline__ void cp16(uint32_t s, const void* g) {
    asm volatile("cp.async.cg.shared.global [%0], [%1], 16;" :: "r"(s), "l"(g));
}
__device__ __forceinline__ void cp_commit() {
    asm volatile("cp.async.commit_group;");
}
__device__ __forceinline__ void cp_wait1() {
    asm volatile("cp.async.wait_group 1;");
}

__device__ __forceinline__ void mma_tf32(float* c, const uint32_t* a, const uint32_t* b) {
    asm volatile(
        "mma.sync.aligned.m16n8k8.row.col.f32.tf32.tf32.f32 "
        "{%0,%1,%2,%3}, {%4,%5,%6,%7}, {%8,%9}, {%0,%1,%2,%3};"
        : "+f"(c[0]), "+f"(c[1]), "+f"(c[2]), "+f"(c[3])
        : "r"(a[0]), "r"(a[1]), "r"(a[2]), "r"(a[3]), "r"(b[0]), "r"(b[1]));
}

// EPI: 0 = bias, 1 = bias + resid, 2 = bias + gelu
// A, W must be 16B-aligned (our scratch). bias/resid may be unaligned (scalar).
template <int EPI>
__global__ void __launch_bounds__(256)
gemm_tc_kernel(const float* __restrict__ A, const float* __restrict__ W,
               const float* __restrict__ bias, const float* __restrict__ resid,
               float* __restrict__ C, int M, int N, int K) {
    extern __shared__ float smem[];
    const uint32_t smem_base = (uint32_t)__cvta_generic_to_shared(smem);

    const int tid = threadIdx.x;
    const int wid = tid >> 5;
    const int lane = tid & 31;
    const int g = lane >> 2;
    const int t = lane & 3;
    const int m0 = blockIdx.y * 128;
    const int n0 = blockIdx.x * 128;
    const int wm = (wid & 1) * 64;
    const int wn = (wid >> 1) * 32;

    const int NK = K >> 5;  // K / 32

    // --- async tile loader: stage s <- k-tile kt ---
    auto load_tile = [&](int s, int kt) {
        int k0 = kt * 32;
        uint32_t sb = smem_base + (uint32_t)(s * STAGE_FLOATS) * 4u;
#pragma unroll
        for (int i = 0; i < 4; i++) {
            int idx = tid + i * 256;
            int ar = idx >> 3, ac4 = idx & 7;
            cp16(sb + (uint32_t)(ar * ASTRIDE + ac4 * 4) * 4u,
                 &A[(size_t)(m0 + ar) * K + k0 + ac4 * 4]);
        }
        uint32_t sbB = sb + (uint32_t)A_TILE * 4u;
#pragma unroll
        for (int i = 0; i < 4; i++) {
            int idx = tid + i * 256;
            int br = idx >> 5, bc4 = idx & 31;
            cp16(sbB + (uint32_t)(br * BSTRIDE + bc4 * 4) * 4u,
                 &W[(size_t)(k0 + br) * N + n0 + bc4 * 4]);
        }
    };

    float acc[4][4][4];
#pragma unroll
    for (int i = 0; i < 4; i++)
#pragma unroll
        for (int j = 0; j < 4; j++)
#pragma unroll
            for (int r = 0; r < 4; r++) acc[i][j][r] = 0.f;

    // prologue: stages 0,1
    load_tile(0, 0); cp_commit();
    load_tile(1, 1); cp_commit();

    for (int k = 0; k < NK; k++) {
        cp_wait1();
        __syncthreads();
        if (k + 2 < NK) load_tile((k + 2) % NSTAGE, k + 2);
        cp_commit();

        const float* As_ = smem + (k % NSTAGE) * STAGE_FLOATS;
        const float* Bs_ = As_ + A_TILE;
#pragma unroll
        for (int ks = 0; ks < 4; ks++) {
            uint32_t a[4][4];
#pragma unroll
            for (int mt = 0; mt < 4; mt++) {
                int r = wm + mt * 16 + g;
                int c = ks * 8 + t;
                a[mt][0] = __float_as_uint(As_[r * ASTRIDE + c]);
                a[mt][1] = __float_as_uint(As_[(r + 8) * ASTRIDE + c]);
                a[mt][2] = __float_as_uint(As_[r * ASTRIDE + c + 4]);
                a[mt][3] = __float_as_uint(As_[(r + 8) * ASTRIDE + c + 4]);
            }
            uint32_t b[4][2];
#pragma unroll
            for (int nt = 0; nt < 4; nt++) {
                int c = wn + nt * 8 + g;
                b[nt][0] = __float_as_uint(Bs_[(ks * 8 + t) * BSTRIDE + c]);
                b[nt][1] = __float_as_uint(Bs_[(ks * 8 + t + 4) * BSTRIDE + c]);
            }
#pragma unroll
            for (int mt = 0; mt < 4; mt++)
#pragma unroll
                for (int nt = 0; nt < 4; nt++)
                    mma_tf32(acc[mt][nt], a[mt], b[nt]);
        }
        __syncthreads();
    }

    // epilogue: c0=(g,2t) c1=(g,2t+1) c2=(g+8,2t) c3=(g+8,2t+1)
#pragma unroll
    for (int mt = 0; mt < 4; mt++) {
#pragma unroll
        for (int nt = 0; nt < 4; nt++) {
            int r0 = m0 + wm + mt * 16 + g;
            int c0 = n0 + wn + nt * 8 + 2 * t;
#pragma unroll
            for (int half = 0; half < 2; half++) {
                int r = r0 + half * 8;
#pragma unroll
                for (int e = 0; e < 2; e++) {
                    int c = c0 + e;
                    float v = acc[mt][nt][half * 2 + e] + bias[c];
                    if (EPI == 1) v += resid[(size_t)r * N + c];
                    if (EPI == 2) {
                        float x = v;
                        float th = tanhf(0.7978845608028654f *
                                         (x + 0.044715f * x * x * x));
                        v = 0.5f * x * (1.f + th);
                    }
                    C[(size_t)r * N + c] = v;
                }
            }
        }
    }
}

// ---------------- RoPE (in-place on q,k of g_qkv) --------------------------
__global__ void rope_kernel(float* __restrict__ qkv, const float* __restrict__ coords,
                            const float* __restrict__ inv_freq) {
    int n = blockIdx.x;
    __shared__ alignas(16) float cs[32];
    __shared__ alignas(16) float sn[32];
    int t = threadIdx.x;
    if (t < 32) {
        int d = t >> 3, f = t & 7;
        float ang = coords[n * 4 + d] * inv_freq[d * 8 + f];
        cs[t] = cosf(ang);
        sn[t] = sinf(ang);
    }
    __syncthreads();
#pragma unroll
    for (int w = t; w < 1024; w += 256) {
        int qk = w >> 9;
        int h = (w >> 5) & 15;
        int p = w & 31;
        float* base = qkv + (size_t)n * QKV3 + qk * EMBED + h * HDIM;
        float x1 = base[p], x2 = base[p + 32];
        base[p]      = x1 * cs[p] - x2 * sn[p];
        base[p + 32] = x2 * cs[p] + x1 * sn[p];
    }
}

// ---------------- Flash-style segment attention ----------------------------
__global__ void __launch_bounds__(64)
attn_kernel(const float* __restrict__ qkv, const int* __restrict__ cu,
            float* __restrict__ out) {
    const int h = blockIdx.y;
    const int tid = threadIdx.x;
    const int qi = blockIdx.x * 64 + tid;

    int s = 0;
#pragma unroll
    for (int i = 1; i <= 7; i++)
        if (cu[i] <= qi) s = i;
    const int kstart = cu[s];
    const int kend = cu[s + 1];

    __shared__ int skb, ske;
    if (tid == 0) { skb = kstart; ske = kend; }
    __syncthreads();
    atomicMin(&skb, kstart);
    atomicMax(&ske, kend);
    __syncthreads();
    const int kb0 = skb & ~63;
    const int keM = ske;

    __shared__ alignas(16) float Ks[64 * 64];
    __shared__ alignas(16) float Vs[64 * 64];

    float q[64], o[64];
    {
        const float* qp = qkv + (size_t)qi * QKV3 + h * HDIM;
#pragma unroll
        for (int d = 0; d < 64; d++) {
            q[d] = qp[d] * 0.125f;
            o[d] = 0.f;
        }
    }
    float m = -1e30f, l = 0.f;

    for (int kt = kb0; kt < keM; kt += 64) {
        {
            int tok = kt + tid;
            const float* kp = qkv + (size_t)tok * QKV3 + EMBED + h * HDIM;
            const float* vp = qkv + (size_t)tok * QKV3 + 2 * EMBED + h * HDIM;
            float4* kd = (float4*)&Ks[tid * 64];
            float4* vd = (float4*)&Vs[tid * 64];
#pragma unroll
            for (int d4 = 0; d4 < 16; d4++) {
                kd[d4] = ((const float4*)kp)[d4];
                vd[d4] = ((const float4*)vp)[d4];
            }
        }
        __syncthreads();

#pragma unroll 1
        for (int jc = 0; jc < 64; jc += 16) {
            float sc[16];
#pragma unroll
            for (int jj = 0; jj < 16; jj++) {
                const float4* kr = (const float4*)&Ks[(jc + jj) * 64];
                float a0 = 0.f, a1 = 0.f, a2 = 0.f, a3 = 0.f;
#pragma unroll
                for (int d4 = 0; d4 < 16; d4++) {
                    float4 kv = kr[d4];
                    a0 = fmaf(q[d4 * 4 + 0], kv.x, a0);
                    a1 = fmaf(q[d4 * 4 + 1], kv.y, a1);
                    a2 = fmaf(q[d4 * 4 + 2], kv.z, a2);
                    a3 = fmaf(q[d4 * 4 + 3], kv.w, a3);
                }
                int kg = kt + jc + jj;
                bool valid = (kg >= kstart) && (kg < kend);
                sc[jj] = valid ? (a0 + a1) + (a2 + a3) : -1e30f;
            }
            float cm = -1e30f;
#pragma unroll
            for (int jj = 0; jj < 16; jj++) cm = fmaxf(cm, sc[jj]);
            float mn = fmaxf(m, cm);
            float scale = expf(m - mn);
            l *= scale;
#pragma unroll
            for (int d = 0; d < 64; d++) o[d] *= scale;
            float p[16];
            float ps = 0.f;
#pragma unroll
            for (int jj = 0; jj < 16; jj++) {
                int kg = kt + jc + jj;
                bool valid = (kg >= kstart) && (kg < kend);
                p[jj] = valid ? expf(sc[jj] - mn) : 0.f;
                ps += p[jj];
            }
            l += ps;
            m = mn;
#pragma unroll
            for (int d4 = 0; d4 < 16; d4++) {
                float o0 = o[d4 * 4 + 0], o1 = o[d4 * 4 + 1];
                float o2 = o[d4 * 4 + 2], o3 = o[d4 * 4 + 3];
#pragma unroll
                for (int jj = 0; jj < 16; jj++) {
                    float4 vv = *(const float4*)&Vs[(jc + jj) * 64 + d4 * 4];
                    o0 = fmaf(p[jj], vv.x, o0);
                    o1 = fmaf(p[jj], vv.y, o1);
                    o2 = fmaf(p[jj], vv.z, o2);
                    o3 = fmaf(p[jj], vv.w, o3);
                }
                o[d4 * 4 + 0] = o0; o[d4 * 4 + 1] = o1;
                o[d4 * 4 + 2] = o2; o[d4 * 4 + 3] = o3;
            }
        }
        __syncthreads();
    }

    float inv_l = 1.f / l;
    float* op = out + (size_t)qi * EMBED + h * HDIM;
#pragma unroll
    for (int d = 0; d < 64; d++) op[d] = o[d] * inv_l;
}

// ---------------- LayerNorm ------------------------------------------------
__device__ __forceinline__ float blockReduceSum(float v) {
    __shared__ alignas(16) float red[8];
    int lane = threadIdx.x & 31, wid = threadIdx.x >> 5;
#pragma unroll
    for (int off = 16; off; off >>= 1) v += __shfl_xor_sync(0xffffffffu, v, off);
    __syncthreads();
    if (lane == 0) red[wid] = v;
    __syncthreads();
    v = (threadIdx.x < 8) ? red[threadIdx.x] : 0.f;
    if (wid == 0) {
#pragma unroll
        for (int off = 4; off; off >>= 1) v += __shfl_xor_sync(0xffu, v, off);
        if (lane == 0) red[0] = v;
    }
    __syncthreads();
    return red[0];
}

__global__ void __launch_bounds__(256)
layernorm_kernel(const float* __restrict__ x, const float* __restrict__ g,
                 const float* __restrict__ b, float* __restrict__ y) {
    int row = blockIdx.x;
    int t = threadIdx.x;
    const float4* xr = (const float4*)(x + (size_t)row * EMBED);
    float4 v = xr[t];
    float s = (v.x + v.y) + (v.z + v.w);
    float mean = blockReduceSum(s) * (1.f / 1024.f);
    float dx = v.x - mean, dy = v.y - mean, dz = v.z - mean, dw = v.w - mean;
    float sq = dx * dx + dy * dy + dz * dz + dw * dw;
    float var = blockReduceSum(sq) * (1.f / 1024.f);
    float rstd = rsqrtf(var + 1e-5f);
    int c = t * 4;
    float g0 = g[c], g1 = g[c + 1], g2 = g[c + 2], g3 = g[c + 3];
    float b0 = b[c], b1 = b[c + 1], b2 = b[c + 2], b3 = b[c + 3];
    float* yr = y + (size_t)row * EMBED + c;
    yr[0] = dx * rstd * g0 + b0;
    yr[1] = dy * rstd * g1 + b1;
    yr[2] = dz * rstd * g2 + b2;
    yr[3] = dw * rstd * g3 + b3;
}

// ---------------- launch ---------------------------------------------------
extern "C" void kernel_launch(void* const* d_in, const int* in_sizes, int n_in,
                              void* d_out, int out_size) {
    const float* coords   = (const float*)d_in[0];
    const float* feats    = (const float*)d_in[1];
    const int*   cu       = (const int*)d_in[2];
    const float* Wqkv     = (const float*)d_in[3];
    const float* bqkv     = (const float*)d_in[4];
    const float* Wo       = (const float*)d_in[5];
    const float* bo       = (const float*)d_in[6];
    const float* inv_freq = (const float*)d_in[7];
    const float* ln1_g    = (const float*)d_in[8];
    const float* ln1_b    = (const float*)d_in[9];
    const float* W1       = (const float*)d_in[10];
    const float* b1       = (const float*)d_in[11];
    const float* W2       = (const float*)d_in[12];
    const float* b2       = (const float*)d_in[13];
    const float* ln2_g    = (const float*)d_in[14];
    const float* ln2_b    = (const float*)d_in[15];
    float* out = (float*)d_out;

    float *qkv, *attn, *res1, *h, *ffn;
    float *feats_a, *wqkv_a, *wo_a, *w1_a, *w2_a;
    cudaGetSymbolAddress((void**)&qkv, g_qkv);
    cudaGetSymbolAddress((void**)&attn, g_attn);
    cudaGetSymbolAddress((void**)&res1, g_res1);
    cudaGetSymbolAddress((void**)&h, g_h);
    cudaGetSymbolAddress((void**)&ffn, g_ffn);
    cudaGetSymbolAddress((void**)&feats_a, g_feats_a);
    cudaGetSymbolAddress((void**)&wqkv_a, g_wqkv);
    cudaGetSymbolAddress((void**)&wo_a, g_wo);
    cudaGetSymbolAddress((void**)&w1_a, g_w1);
    cudaGetSymbolAddress((void**)&w2_a, g_w2);

    // raise dynamic smem cap for gemm instantiations (host-side, idempotent)
    cudaFuncSetAttribute(gemm_tc_kernel<0>,
                         cudaFuncAttributeMaxDynamicSharedMemorySize, GEMM_SMEM_BYTES);
    cudaFuncSetAttribute(gemm_tc_kernel<1>,
                         cudaFuncAttributeMaxDynamicSharedMemorySize, GEMM_SMEM_BYTES);
    cudaFuncSetAttribute(gemm_tc_kernel<2>,
                         cudaFuncAttributeMaxDynamicSharedMemorySize, GEMM_SMEM_BYTES);

    // 0. align + tf32-round unaligned inputs
    copy_tf32_kernel<<<(N_TOK * EMBED) / 256, 256>>>(feats, feats_a, N_TOK * EMBED);
    copy_tf32_kernel<<<(EMBED * QKV3) / 256, 256>>>(Wqkv, wqkv_a, EMBED * QKV3);
    copy_tf32_kernel<<<(EMBED * EMBED) / 256, 256>>>(Wo, wo_a, EMBED * EMBED);
    copy_tf32_kernel<<<(EMBED * FFN) / 256, 256>>>(W1, w1_a, EMBED * FFN);
    copy_tf32_kernel<<<(FFN * EMBED) / 256, 256>>>(W2, w2_a, FFN * EMBED);

    // 1. QKV projection
    gemm_tc_kernel<0><<<dim3(QKV3 / 128, N_TOK / 128), 256, GEMM_SMEM_BYTES>>>(
        feats_a, wqkv_a, bqkv, nullptr, qkv, N_TOK, QKV3, EMBED);
    // 2. RoPE on q,k
    rope_kernel<<<N_TOK, 256>>>(qkv, coords, inv_freq);
    // 3. Segment attention
    attn_kernel<<<dim3(N_TOK / 64, NHEAD), 64>>>(qkv, cu, attn);
    // 4. Wo projection + residual(original feats)
    gemm_tc_kernel<1><<<dim3(EMBED / 128, N_TOK / 128), 256, GEMM_SMEM_BYTES>>>(
        attn, wo_a, bo, feats, res1, N_TOK, EMBED, EMBED);
    // 5. LN1 -> h
    layernorm_kernel<<<N_TOK, 256>>>(res1, ln1_g, ln1_b, h);
    // 6. FFN up + gelu
    gemm_tc_kernel<2><<<dim3(FFN / 128, N_TOK / 128), 256, GEMM_SMEM_BYTES>>>(
        h, w1_a, b1, nullptr, ffn, N_TOK, FFN, EMBED);
    // 7. FFN down + residual(h)
    gemm_tc_kernel<1><<<dim3(EMBED / 128, N_TOK / 128), 256, GEMM_SMEM_BYTES>>>(
        ffn, w2_a, b2, h, res1, N_TOK, EMBED, FFN);
    // 8. LN2 -> out
    layernorm_kernel<<<N_TOK, 256>>>(res1, ln2_g, ln2_b, out);
}

// round 6
// speedup vs baseline: 2.0282x; 1.0465x over previous
#include <cuda_runtime.h>
#include <cuda_bf16.h>
#include <math.h>
#include <stdint.h>

#define N_TOK 4096
#define EMBED 1024
#define NHEAD 16
#define HDIM 64
#define FFN 4096
#define QKV3 3072

// ---------------- scratch (device globals; no cudaMalloc allowed) ----------
__device__ alignas(16) float g_qkv[N_TOK * QKV3];
__device__ alignas(16) float g_attn[N_TOK * EMBED];
__device__ alignas(16) float g_res1[N_TOK * EMBED];
__device__ alignas(16) float g_h[N_TOK * EMBED];
__device__ alignas(16) float g_ffn[N_TOK * FFN];
// aligned (+tf32-rounded) copies of unaligned harness inputs
__device__ alignas(16) float g_feats_a[N_TOK * EMBED];
__device__ alignas(16) float g_wqkv[EMBED * QKV3];
__device__ alignas(16) float g_wo[EMBED * EMBED];
__device__ alignas(16) float g_w1[EMBED * FFN];
__device__ alignas(16) float g_w2[FFN * EMBED];

__device__ __forceinline__ uint32_t f2tf32(float x) {
    uint32_t u;
    asm("cvt.rna.tf32.f32 %0, %1;" : "=r"(u) : "f"(x));
    return u;
}

__global__ void copy_tf32_kernel(const float* __restrict__ src,
                                 float* __restrict__ dst, int n) {
    int i = blockIdx.x * blockDim.x + threadIdx.x;
    if (i < n) dst[i] = __uint_as_float(f2tf32(src[i]));
}

// ---------------- TF32 tensor-core GEMM, 128x256 block tile, 3-stage -------
#define NSTAGE 3
#define BM 128
#define BN 256
#define BK 32
#define ASTRIDE 36     // 32 + 4 pad; bank(4g+t) conflict-free
#define BSTRIDE 264    // 256 + 8 pad; 264 % 32 == 8 -> bank(8t+g) conflict-free
#define A_TILE (BM * ASTRIDE)
#define B_TILE (BK * BSTRIDE)
#define STAGE_FLOATS (A_TILE + B_TILE)
#define GEMM_SMEM_BYTES (NSTAGE * STAGE_FLOATS * 4)

__device__ __forceinline__ void cp16(uint32_t s, const void* g) {
    asm volatile("cp.async.cg.shared.global [%0], [%1], 16;" :: "r"(s), "l"(g));
}
__device__ __forceinline__ void cp_commit() {
    asm volatile("cp.async.commit_group;");
}
__device__ __forceinline__ void cp_wait1() {
    asm volatile("cp.async.wait_group 1;");
}

__device__ __forceinline__ void mma_tf32(float* c, const uint32_t* a, const uint32_t* b) {
    asm volatile(
        "mma.sync.aligned.m16n8k8.row.col.f32.tf32.tf32.f32 "
        "{%0,%1,%2,%3}, {%4,%5,%6,%7}, {%8,%9}, {%0,%1,%2,%3};"
        : "+f"(c[0]), "+f"(c[1]), "+f"(c[2]), "+f"(c[3])
        : "r"(a[0]), "r"(a[1]), "r"(a[2]), "r"(a[3]), "r"(b[0]), "r"(b[1]));
}

// EPI: 0 = bias, 1 = bias + resid, 2 = bias + gelu
template <int EPI>
__global__ void __launch_bounds__(256, 1)
gemm_tc_kernel(const float* __restrict__ A, const float* __restrict__ W,
               const float* __restrict__ bias, const float* __restrict__ resid,
               float* __restrict__ C, int M, int N, int K) {
    extern __shared__ float smem[];
    const uint32_t smem_base = (uint32_t)__cvta_generic_to_shared(smem);

    const int tid = threadIdx.x;
    const int wid = tid >> 5;
    const int lane = tid & 31;
    const int g = lane >> 2;
    const int t = lane & 3;
    const int m0 = blockIdx.y * BM;
    const int n0 = blockIdx.x * BN;
    const int wm = (wid & 1) * 64;     // 2 warps over M
    const int wn = (wid >> 1) * 64;    // 4 warps over N

    const int NK = K >> 5;

    auto load_tile = [&](int s, int kt) {
        int k0 = kt * BK;
        uint32_t sb = smem_base + (uint32_t)(s * STAGE_FLOATS) * 4u;
        // A: 128x32 = 1024 float4 ops, 4 per thread
#pragma unroll
        for (int i = 0; i < 4; i++) {
            int idx = tid + i * 256;
            int ar = idx >> 3, ac4 = idx & 7;
            cp16(sb + (uint32_t)(ar * ASTRIDE + ac4 * 4) * 4u,
                 &A[(size_t)(m0 + ar) * K + k0 + ac4 * 4]);
        }
        // B: 32x256 = 2048 float4 ops, 8 per thread
        uint32_t sbB = sb + (uint32_t)A_TILE * 4u;
#pragma unroll
        for (int i = 0; i < 8; i++) {
            int idx = tid + i * 256;
            int br = idx >> 6, bc4 = idx & 63;
            cp16(sbB + (uint32_t)(br * BSTRIDE + bc4 * 4) * 4u,
                 &W[(size_t)(k0 + br) * N + n0 + bc4 * 4]);
        }
    };

    float acc[4][8][4];
#pragma unroll
    for (int i = 0; i < 4; i++)
#pragma unroll
        for (int j = 0; j < 8; j++)
#pragma unroll
            for (int r = 0; r < 4; r++) acc[i][j][r] = 0.f;

    load_tile(0, 0); cp_commit();
    load_tile(1, 1); cp_commit();

    for (int k = 0; k < NK; k++) {
        cp_wait1();
        __syncthreads();
        if (k + 2 < NK) load_tile((k + 2) % NSTAGE, k + 2);
        cp_commit();

        const float* As_ = smem + (k % NSTAGE) * STAGE_FLOATS;
        const float* Bs_ = As_ + A_TILE;
#pragma unroll
        for (int ks = 0; ks < 4; ks++) {
            uint32_t a[4][4];
#pragma unroll
            for (int mt = 0; mt < 4; mt++) {
                int r = wm + mt * 16 + g;
                int c = ks * 8 + t;
                a[mt][0] = __float_as_uint(As_[r * ASTRIDE + c]);
                a[mt][1] = __float_as_uint(As_[(r + 8) * ASTRIDE + c]);
                a[mt][2] = __float_as_uint(As_[r * ASTRIDE + c + 4]);
                a[mt][3] = __float_as_uint(As_[(r + 8) * ASTRIDE + c + 4]);
            }
            uint32_t b[8][2];
#pragma unroll
            for (int nt = 0; nt < 8; nt++) {
                int c = wn + nt * 8 + g;
                b[nt][0] = __float_as_uint(Bs_[(ks * 8 + t) * BSTRIDE + c]);
                b[nt][1] = __float_as_uint(Bs_[(ks * 8 + t + 4) * BSTRIDE + c]);
            }
#pragma unroll
            for (int mt = 0; mt < 4; mt++)
#pragma unroll
                for (int nt = 0; nt < 8; nt++)
                    mma_tf32(acc[mt][nt], a[mt], b[nt]);
        }
        __syncthreads();
    }

#pragma unroll
    for (int mt = 0; mt < 4; mt++) {
#pragma unroll
        for (int nt = 0; nt < 8; nt++) {
            int r0 = m0 + wm + mt * 16 + g;
            int c0 = n0 + wn + nt * 8 + 2 * t;
#pragma unroll
            for (int half = 0; half < 2; half++) {
                int r = r0 + half * 8;
#pragma unroll
                for (int e = 0; e < 2; e++) {
                    int c = c0 + e;
                    float v = acc[mt][nt][half * 2 + e] + bias[c];
                    if (EPI == 1) v += resid[(size_t)r * N + c];
                    if (EPI == 2) {
                        float x = v;
                        float th = tanhf(0.7978845608028654f *
                                         (x + 0.044715f * x * x * x));
                        v = 0.5f * x * (1.f + th);
                    }
                    C[(size_t)r * N + c] = v;
                }
            }
        }
    }
}

// ---------------- RoPE (in-place on q,k of g_qkv) --------------------------
__global__ void rope_kernel(float* __restrict__ qkv, const float* __restrict__ coords,
                            const float* __restrict__ inv_freq) {
    int n = blockIdx.x;
    __shared__ alignas(16) float cs[32];
    __shared__ alignas(16) float sn[32];
    int t = threadIdx.x;
    if (t < 32) {
        int d = t >> 3, f = t & 7;
        float ang = coords[n * 4 + d] * inv_freq[d * 8 + f];
        cs[t] = cosf(ang);
        sn[t] = sinf(ang);
    }
    __syncthreads();
#pragma unroll
    for (int w = t; w < 1024; w += 256) {
        int qk = w >> 9;
        int h = (w >> 5) & 15;
        int p = w & 31;
        float* base = qkv + (size_t)n * QKV3 + qk * EMBED + h * HDIM;
        float x1 = base[p], x2 = base[p + 32];
        base[p]      = x1 * cs[p] - x2 * sn[p];
        base[p + 32] = x2 * cs[p] + x1 * sn[p];
    }
}

// ---------------- Flash-style segment attention ----------------------------
__global__ void __launch_bounds__(64)
attn_kernel(const float* __restrict__ qkv, const int* __restrict__ cu,
            float* __restrict__ out) {
    const int h = blockIdx.y;
    const int tid = threadIdx.x;
    const int qi = blockIdx.x * 64 + tid;

    int s = 0;
#pragma unroll
    for (int i = 1; i <= 7; i++)
        if (cu[i] <= qi) s = i;
    const int kstart = cu[s];
    const int kend = cu[s + 1];

    __shared__ int skb, ske;
    if (tid == 0) { skb = kstart; ske = kend; }
    __syncthreads();
    atomicMin(&skb, kstart);
    atomicMax(&ske, kend);
    __syncthreads();
    const int kb0 = skb & ~63;
    const int keM = ske;

    __shared__ alignas(16) float Ks[64 * 64];
    __shared__ alignas(16) float Vs[64 * 64];

    float q[64], o[64];
    {
        const float* qp = qkv + (size_t)qi * QKV3 + h * HDIM;
#pragma unroll
        for (int d = 0; d < 64; d++) {
            q[d] = qp[d] * 0.125f;
            o[d] = 0.f;
        }
    }
    float m = -1e30f, l = 0.f;

    for (int kt = kb0; kt < keM; kt += 64) {
        {
            int tok = kt + tid;
            const float* kp = qkv + (size_t)tok * QKV3 + EMBED + h * HDIM;
            const float* vp = qkv + (size_t)tok * QKV3 + 2 * EMBED + h * HDIM;
            float4* kd = (float4*)&Ks[tid * 64];
            float4* vd = (float4*)&Vs[tid * 64];
#pragma unroll
            for (int d4 = 0; d4 < 16; d4++) {
                kd[d4] = ((const float4*)kp)[d4];
                vd[d4] = ((const float4*)vp)[d4];
            }
        }
        __syncthreads();

#pragma unroll 1
        for (int jc = 0; jc < 64; jc += 16) {
            float sc[16];
#pragma unroll
            for (int jj = 0; jj < 16; jj++) {
                const float4* kr = (const float4*)&Ks[(jc + jj) * 64];
                float a0 = 0.f, a1 = 0.f, a2 = 0.f, a3 = 0.f;
#pragma unroll
                for (int d4 = 0; d4 < 16; d4++) {
                    float4 kv = kr[d4];
                    a0 = fmaf(q[d4 * 4 + 0], kv.x, a0);
                    a1 = fmaf(q[d4 * 4 + 1], kv.y, a1);
                    a2 = fmaf(q[d4 * 4 + 2], kv.z, a2);
                    a3 = fmaf(q[d4 * 4 + 3], kv.w, a3);
                }
                int kg = kt + jc + jj;
                bool valid = (kg >= kstart) && (kg < kend);
                sc[jj] = valid ? (a0 + a1) + (a2 + a3) : -1e30f;
            }
            float cm = -1e30f;
#pragma unroll
            for (int jj = 0; jj < 16; jj++) cm = fmaxf(cm, sc[jj]);
            float mn = fmaxf(m, cm);
            float scale = expf(m - mn);
            l *= scale;
#pragma unroll
            for (int d = 0; d < 64; d++) o[d] *= scale;
            float p[16];
            float ps = 0.f;
#pragma unroll
            for (int jj = 0; jj < 16; jj++) {
                int kg = kt + jc + jj;
                bool valid = (kg >= kstart) && (kg < kend);
                p[jj] = valid ? expf(sc[jj] - mn) : 0.f;
                ps += p[jj];
            }
            l += ps;
            m = mn;
#pragma unroll
            for (int d4 = 0; d4 < 16; d4++) {
                float o0 = o[d4 * 4 + 0], o1 = o[d4 * 4 + 1];
                float o2 = o[d4 * 4 + 2], o3 = o[d4 * 4 + 3];
#pragma unroll
                for (int jj = 0; jj < 16; jj++) {
                    float4 vv = *(const float4*)&Vs[(jc + jj) * 64 + d4 * 4];
                    o0 = fmaf(p[jj], vv.x, o0);
                    o1 = fmaf(p[jj], vv.y, o1);
                    o2 = fmaf(p[jj], vv.z, o2);
                    o3 = fmaf(p[jj], vv.w, o3);
                }
                o[d4 * 4 + 0] = o0; o[d4 * 4 + 1] = o1;
                o[d4 * 4 + 2] = o2; o[d4 * 4 + 3] = o3;
            }
        }
        __syncthreads();
    }

    float inv_l = 1.f / l;
    float* op = out + (size_t)qi * EMBED + h * HDIM;
#pragma unroll
    for (int d = 0; d < 64; d++) op[d] = o[d] * inv_l;
}

// ---------------- LayerNorm ------------------------------------------------
__device__ __forceinline__ float blockReduceSum(float v) {
    __shared__ alignas(16) float red[8];
    int lane = threadIdx.x & 31, wid = threadIdx.x >> 5;
#pragma unroll
    for (int off = 16; off; off >>= 1) v += __shfl_xor_sync(0xffffffffu, v, off);
    __syncthreads();
    if (lane == 0) red[wid] = v;
    __syncthreads();
    v = (threadIdx.x < 8) ? red[threadIdx.x] : 0.f;
    if (wid == 0) {
#pragma unroll
        for (int off = 4; off; off >>= 1) v += __shfl_xor_sync(0xffu, v, off);
        if (lane == 0) red[0] = v;
    }
    __syncthreads();
    return red[0];
}

__global__ void __launch_bounds__(256)
layernorm_kernel(const float* __restrict__ x, const float* __restrict__ g,
                 const float* __restrict__ b, float* __restrict__ y) {
    int row = blockIdx.x;
    int t = threadIdx.x;
    const float4* xr = (const float4*)(x + (size_t)row * EMBED);
    float4 v = xr[t];
    float s = (v.x + v.y) + (v.z + v.w);
    float mean = blockReduceSum(s) * (1.f / 1024.f);
    float dx = v.x - mean, dy = v.y - mean, dz = v.z - mean, dw = v.w - mean;
    float sq = dx * dx + dy * dy + dz * dz + dw * dw;
    float var = blockReduceSum(sq) * (1.f / 1024.f);
    float rstd = rsqrtf(var + 1e-5f);
    int c = t * 4;
    float g0 = g[c], g1 = g[c + 1], g2 = g[c + 2], g3 = g[c + 3];
    float b0 = b[c], b1 = b[c + 1], b2 = b[c + 2], b3 = b[c + 3];
    float* yr = y + (size_t)row * EMBED + c;
    yr[0] = dx * rstd * g0 + b0;
    yr[1] = dy * rstd * g1 + b1;
    yr[2] = dz * rstd * g2 + b2;
    yr[3] = dw * rstd * g3 + b3;
}

// ---------------- launch ---------------------------------------------------
extern "C" void kernel_launch(void* const* d_in, const int* in_sizes, int n_in,
                              void* d_out, int out_size) {
    const float* coords   = (const float*)d_in[0];
    const float* feats    = (const float*)d_in[1];
    const int*   cu       = (const int*)d_in[2];
    const float* Wqkv     = (const float*)d_in[3];
    const float* bqkv     = (const float*)d_in[4];
    const float* Wo       = (const float*)d_in[5];
    const float* bo       = (const float*)d_in[6];
    const float* inv_freq = (const float*)d_in[7];
    const float* ln1_g    = (const float*)d_in[8];
    const float* ln1_b    = (const float*)d_in[9];
    const float* W1       = (const float*)d_in[10];
    const float* b1       = (const float*)d_in[11];
    const float* W2       = (const float*)d_in[12];
    const float* b2       = (const float*)d_in[13];
    const float* ln2_g    = (const float*)d_in[14];
    const float* ln2_b    = (const float*)d_in[15];
    float* out = (float*)d_out;

    float *qkv, *attn, *res1, *h, *ffn;
    float *feats_a, *wqkv_a, *wo_a, *w1_a, *w2_a;
    cudaGetSymbolAddress((void**)&qkv, g_qkv);
    cudaGetSymbolAddress((void**)&attn, g_attn);
    cudaGetSymbolAddress((void**)&res1, g_res1);
    cudaGetSymbolAddress((void**)&h, g_h);
    cudaGetSymbolAddress((void**)&ffn, g_ffn);
    cudaGetSymbolAddress((void**)&feats_a, g_feats_a);
    cudaGetSymbolAddress((void**)&wqkv_a, g_wqkv);
    cudaGetSymbolAddress((void**)&wo_a, g_wo);
    cudaGetSymbolAddress((void**)&w1_a, g_w1);
    cudaGetSymbolAddress((void**)&w2_a, g_w2);

    cudaFuncSetAttribute(gemm_tc_kernel<0>,
                         cudaFuncAttributeMaxDynamicSharedMemorySize, GEMM_SMEM_BYTES);
    cudaFuncSetAttribute(gemm_tc_kernel<1>,
                         cudaFuncAttributeMaxDynamicSharedMemorySize, GEMM_SMEM_BYTES);
    cudaFuncSetAttribute(gemm_tc_kernel<2>,
                         cudaFuncAttributeMaxDynamicSharedMemorySize, GEMM_SMEM_BYTES);

    // 0. align + tf32-round unaligned inputs
    copy_tf32_kernel<<<(N_TOK * EMBED) / 256, 256>>>(feats, feats_a, N_TOK * EMBED);
    copy_tf32_kernel<<<(EMBED * QKV3) / 256, 256>>>(Wqkv, wqkv_a, EMBED * QKV3);
    copy_tf32_kernel<<<(EMBED * EMBED) / 256, 256>>>(Wo, wo_a, EMBED * EMBED);
    copy_tf32_kernel<<<(EMBED * FFN) / 256, 256>>>(W1, w1_a, EMBED * FFN);
    copy_tf32_kernel<<<(FFN * EMBED) / 256, 256>>>(W2, w2_a, FFN * EMBED);

    // 1. QKV projection
    gemm_tc_kernel<0><<<dim3(QKV3 / BN, N_TOK / BM), 256, GEMM_SMEM_BYTES>>>(
        feats_a, wqkv_a, bqkv, nullptr, qkv, N_TOK, QKV3, EMBED);
    // 2. RoPE on q,k
    rope_kernel<<<N_TOK, 256>>>(qkv, coords, inv_freq);
    // 3. Segment attention
    attn_kernel<<<dim3(N_TOK / 64, NHEAD), 64>>>(qkv, cu, attn);
    // 4. Wo projection + residual(original feats)
    gemm_tc_kernel<1><<<dim3(EMBED / BN, N_TOK / BM), 256, GEMM_SMEM_BYTES>>>(
        attn, wo_a, bo, feats, res1, N_TOK, EMBED, EMBED);
    // 5. LN1 -> h
    layernorm_kernel<<<N_TOK, 256>>>(res1, ln1_g, ln1_b, h);
    // 6. FFN up + gelu
    gemm_tc_kernel<2><<<dim3(FFN / BN, N_TOK / BM), 256, GEMM_SMEM_BYTES>>>(
        h, w1_a, b1, nullptr, ffn, N_TOK, FFN, EMBED);
    // 7. FFN down + residual(h)
    gemm_tc_kernel<1><<<dim3(EMBED / BN, N_TOK / BM), 256, GEMM_SMEM_BYTES>>>(
        ffn, w2_a, b2, h, res1, N_TOK, EMBED, FFN);
    // 8. LN2 -> out
    layernorm_kernel<<<N_TOK, 256>>>(res1, ln2_g, ln2_b, out);
}